// round 7
// baseline (speedup 1.0000x reference)
#include <cuda_runtime.h>
#include <cuda_bf16.h>
#include <math.h>
#include <stdint.h>

#define GMM_D 64
#define GMM_K 64
#define BS    128
#define TPB   128

// padded row stride: 136 bf16 = 272 B (rows walk 4B-banks in steps of 4 -> ldmatrix conflict-free)
#define RSA 272
#define RSW 272
#define RSO 132                           // epilogue sO row stride (floats)

// smem layout (bytes)
#define OFF_A1 0                          // X' hi : 128 x 136 bf16 (sO overlays this after MMA)
#define OFF_A2 (OFF_A1 + 128 * RSA)       // X' lo
#define OFF_W1 (OFF_A2 + 128 * RSA)       // W  hi : 64 x 136 bf16
#define OFF_W2 (OFF_W1 + 64 * RSW)        // W  lo
#define OFF_C  (OFF_W2 + 64 * RSW)        // 64 floats
#define SMEM_TOTAL (OFF_C + 256)          // 104704 B -> 2 CTAs/SM

#define OFF_LSE (OFF_A1 + 64 * RSO * 4)   // 128 floats inside dead A region

// ---------------- helpers ----------------
__device__ __forceinline__ uint32_t smem_u32(const void* p) {
    uint32_t a;
    asm("{ .reg .u64 t; cvta.to.shared.u64 t, %1; cvt.u32.u64 %0, t; }" : "=r"(a) : "l"(p));
    return a;
}
__device__ __forceinline__ uint32_t bf16x2_rn(float lo, float hi) {
    uint32_t r;
    asm("cvt.rn.satfinite.bf16x2.f32 %0, %1, %2;" : "=r"(r) : "f"(hi), "f"(lo));
    return r;
}
__device__ __forceinline__ float lof(uint32_t p) { return __uint_as_float(p << 16); }
__device__ __forceinline__ float hif(uint32_t p) { return __uint_as_float(p & 0xffff0000u); }

__device__ __forceinline__ void ldsm4(uint32_t& r0, uint32_t& r1, uint32_t& r2, uint32_t& r3,
                                      uint32_t a) {
    asm volatile("ldmatrix.sync.aligned.m8n8.x4.shared.b16 {%0,%1,%2,%3}, [%4];"
                 : "=r"(r0), "=r"(r1), "=r"(r2), "=r"(r3) : "r"(a));
}
__device__ __forceinline__ void mma16816(float* d, const uint32_t* a, const uint32_t* b) {
    asm volatile(
        "mma.sync.aligned.m16n8k16.row.col.f32.bf16.bf16.f32 "
        "{%0,%1,%2,%3}, {%4,%5,%6,%7}, {%8,%9}, {%0,%1,%2,%3};"
        : "+f"(d[0]), "+f"(d[1]), "+f"(d[2]), "+f"(d[3])
        : "r"(a[0]), "r"(a[1]), "r"(a[2]), "r"(a[3]), "r"(b[0]), "r"(b[1]));
}

// load one ks-step of fragments: 4 m16 A tiles (hi+lo) + 4 n8 B tiles (hi+lo)
__device__ __forceinline__ void load_frags(uint32_t a_base, uint32_t b_base, int ks,
                                           uint32_t a1f[4][4], uint32_t a2f[4][4],
                                           uint32_t b1f[4][2], uint32_t b2f[4][2]) {
    #pragma unroll
    for (int mi = 0; mi < 4; mi++) {
        uint32_t aa = a_base + mi * (16 * RSA) + ks * 32;
        ldsm4(a1f[mi][0], a1f[mi][1], a1f[mi][2], a1f[mi][3], aa);
        ldsm4(a2f[mi][0], a2f[mi][1], a2f[mi][2], a2f[mi][3], aa + (OFF_A2 - OFF_A1));
    }
    #pragma unroll
    for (int p = 0; p < 2; p++) {
        uint32_t ba = b_base + p * (16 * RSW) + ks * 32;
        ldsm4(b1f[2 * p][0], b1f[2 * p][1], b1f[2 * p + 1][0], b1f[2 * p + 1][1], ba);
        ldsm4(b2f[2 * p][0], b2f[2 * p][1], b2f[2 * p + 1][0], b2f[2 * p + 1][1],
              ba + (OFF_W2 - OFF_W1));
    }
}

// ---------------------------------------------------------------------------
// Fused GMM posterior via HMMA (bf16 3-product fp32 reconstruction).
// D[n,c] = sum_j X'[n,j]*W[c,j];  X'=[x, x^2], W=[mu e^{-lv}, -0.5 e^{-lv}]
// C[c] = -0.5*sum_d(lv + mu^2 e^{-lv}) + lp[c]  (k-uniform terms cancel)
// Block: 128 samples x 64 comps. Warp (rw=warp&1, cw=warp>>1): rows rw*64+ (4 m16),
// cols cw*32+ (4 n8).
// ---------------------------------------------------------------------------
__global__ void __launch_bounds__(TPB, 2)
gmm_fused(const float* __restrict__ X, const float* __restrict__ mu,
          const float* __restrict__ lv, const float* __restrict__ lp,
          float* __restrict__ out, int N) {
    extern __shared__ char sm[];
    const uint32_t smb = smem_u32(sm);
    const int t  = threadIdx.x;
    const int n0 = blockIdx.x * BS;
    float* sC = (float*)(sm + OFF_C);

    // ---- stage W hi/lo tiles ----
    #pragma unroll
    for (int i = 0; i < 16; i++) {
        int idx = i * TPB + t;            // 0..2047 pair slots
        int k   = idx >> 5;
        int d   = (idx & 31) * 2;
        float l0 = lv[k * GMM_D + d],  l1 = lv[k * GMM_D + d + 1];
        float m0 = mu[k * GMM_D + d],  m1 = mu[k * GMM_D + d + 1];
        float e0 = __expf(-l0), e1 = __expf(-l1);
        float wa0 = m0 * e0,    wa1 = m1 * e1;       // j = d
        float wb0 = -0.5f * e0, wb1 = -0.5f * e1;    // j = 64 + d
        uint32_t ah = bf16x2_rn(wa0, wa1);
        uint32_t al = bf16x2_rn(wa0 - lof(ah), wa1 - hif(ah));
        uint32_t bh = bf16x2_rn(wb0, wb1);
        uint32_t bl = bf16x2_rn(wb0 - lof(bh), wb1 - hif(bh));
        char* r1 = sm + OFF_W1 + k * RSW;
        char* r2 = sm + OFF_W2 + k * RSW;
        *(uint32_t*)(r1 + d * 2)       = ah;
        *(uint32_t*)(r1 + 128 + d * 2) = bh;
        *(uint32_t*)(r2 + d * 2)       = al;
        *(uint32_t*)(r2 + 128 + d * 2) = bl;
    }

    // ---- stage X' hi/lo tiles ----
    {
        const float4* xg4 = (const float4*)(X + (size_t)n0 * GMM_D);
        #pragma unroll
        for (int i = 0; i < 16; i++) {
            int idx = i * TPB + t;        // 0..2047 float4 slots
            int n   = idx >> 4;
            int d0  = (idx & 15) * 4;
            float4 v = xg4[idx];
            uint32_t h01 = bf16x2_rn(v.x, v.y);
            uint32_t h23 = bf16x2_rn(v.z, v.w);
            uint32_t l01 = bf16x2_rn(v.x - lof(h01), v.y - hif(h01));
            uint32_t l23 = bf16x2_rn(v.z - lof(h23), v.w - hif(h23));
            float s0 = v.x * v.x, s1 = v.y * v.y, s2 = v.z * v.z, s3 = v.w * v.w;
            uint32_t sh01 = bf16x2_rn(s0, s1);
            uint32_t sh23 = bf16x2_rn(s2, s3);
            uint32_t sl01 = bf16x2_rn(s0 - lof(sh01), s1 - hif(sh01));
            uint32_t sl23 = bf16x2_rn(s2 - lof(sh23), s3 - hif(sh23));
            char* r1 = sm + OFF_A1 + n * RSA;
            char* r2 = sm + OFF_A2 + n * RSA;
            *(uint2*)(r1 + d0 * 2)       = make_uint2(h01, h23);
            *(uint2*)(r1 + 128 + d0 * 2) = make_uint2(sh01, sh23);
            *(uint2*)(r2 + d0 * 2)       = make_uint2(l01, l23);
            *(uint2*)(r2 + 128 + d0 * 2) = make_uint2(sl01, sl23);
        }
    }

    // ---- per-component constant ----
    if (t < GMM_K) {
        float s = 0.f;
        #pragma unroll 8
        for (int d = 0; d < GMM_D; d++) {
            float l = lv[t * GMM_D + d];
            float m = mu[t * GMM_D + d];
            s += l + m * m * __expf(-l);
        }
        sC[t] = -0.5f * s + lp[t];
    }
    __syncthreads();

    // ---- main HMMA loop (warp tile 64 rows x 32 cols, double-buffered frags) ----
    const int lane = t & 31;
    const int warp = t >> 5;
    const int rw   = warp & 1;
    const int cw   = warp >> 1;
    const int gid  = lane >> 2;
    const int tig  = lane & 3;
    const int g    = lane >> 3;

    const uint32_t a_base = smb + OFF_A1
                          + (uint32_t)(rw * 64 + (lane & 15)) * RSA
                          + (uint32_t)((lane >> 4) * 16);
    const uint32_t b_base = smb + OFF_W1
                          + (uint32_t)(cw * 32 + (g >> 1) * 8 + (lane & 7)) * RSW
                          + (uint32_t)((g & 1) * 16);

    float acc[4][4][4];
    #pragma unroll
    for (int mi = 0; mi < 4; mi++)
        #pragma unroll
        for (int nt = 0; nt < 4; nt++)
            #pragma unroll
            for (int r = 0; r < 4; r++) acc[mi][nt][r] = 0.f;

    uint32_t a1f[2][4][4], a2f[2][4][4], b1f[2][4][2], b2f[2][4][2];
    load_frags(a_base, b_base, 0, a1f[0], a2f[0], b1f[0], b2f[0]);

    #pragma unroll
    for (int ks = 0; ks < 8; ks++) {
        const int cur = ks & 1;
        if (ks < 7)
            load_frags(a_base, b_base, ks + 1, a1f[cur ^ 1], a2f[cur ^ 1],
                       b1f[cur ^ 1], b2f[cur ^ 1]);
        #pragma unroll
        for (int mi = 0; mi < 4; mi++)
            #pragma unroll
            for (int nt = 0; nt < 4; nt++) {
                mma16816(acc[mi][nt], a1f[cur][mi], b1f[cur][nt]);   // x1*w1
                mma16816(acc[mi][nt], a1f[cur][mi], b2f[cur][nt]);   // x1*w2
                mma16816(acc[mi][nt], a2f[cur][mi], b1f[cur][nt]);   // x2*w1
            }
    }

    __syncthreads();   // A tiles dead -> sO overlay

    // ---- scatter weighted to sO[k][n] (+C), conflict-free ----
    float* sO = (float*)(sm + OFF_A1);
    #pragma unroll
    for (int nt = 0; nt < 4; nt++) {
        const int k0 = cw * 32 + nt * 8 + 2 * tig;
        const float c0 = sC[k0], c1 = sC[k0 + 1];
        #pragma unroll
        for (int mi = 0; mi < 4; mi++) {
            const int nl = rw * 64 + mi * 16 + gid;
            sO[k0 * RSO + nl]           = acc[mi][nt][0] + c0;
            sO[(k0 + 1) * RSO + nl]     = acc[mi][nt][1] + c1;
            sO[k0 * RSO + nl + 8]       = acc[mi][nt][2] + c0;
            sO[(k0 + 1) * RSO + nl + 8] = acc[mi][nt][3] + c1;
        }
    }
    __syncthreads();

    // ---- per-sample logsumexp over k ----
    float* sLse = (float*)(sm + OFF_LSE);
    {
        float mx = -INFINITY;
        #pragma unroll 8
        for (int k = 0; k < GMM_K; k++) mx = fmaxf(mx, sO[k * RSO + t]);
        float s = 0.f;
        #pragma unroll 8
        for (int k = 0; k < GMM_K; k++) s += __expf(sO[k * RSO + t] - mx);
        sLse[t] = mx + __logf(s);
    }
    __syncthreads();

    // ---- coalesced float4 writeout ----
    {
        const int kq = t >> 5;
        float4 L = ((const float4*)sLse)[lane];
        #pragma unroll
        for (int i = 0; i < 16; i++) {
            int k = i * 4 + kq;
            float4 v = *(const float4*)&sO[k * RSO + lane * 4];
            float4 r;
            r.x = v.x - L.x; r.y = v.y - L.y; r.z = v.z - L.z; r.w = v.w - L.w;
            *(float4*)(out + (size_t)k * N + n0 + lane * 4) = r;
        }
    }
}

extern "C" void kernel_launch(void* const* d_in, const int* in_sizes, int n_in,
                              void* d_out, int out_size) {
    const float* X  = (const float*)d_in[0];
    const float* mu = (const float*)d_in[1];
    const float* lv = (const float*)d_in[2];
    const float* lp = (const float*)d_in[3];
    float* out = (float*)d_out;

    const int K = in_sizes[3];            // 64
    const int D = in_sizes[1] / K;        // 64
    const int N = in_sizes[0] / D;        // 131072

    cudaFuncSetAttribute(gmm_fused, cudaFuncAttributeMaxDynamicSharedMemorySize, SMEM_TOTAL);
    gmm_fused<<<N / BS, TPB, SMEM_TOTAL>>>(X, mu, lv, lp, out, N);
}

// round 9
// speedup vs baseline: 1.0540x; 1.0540x over previous
#include <cuda_runtime.h>
#include <cuda_bf16.h>
#include <math.h>
#include <stdint.h>

#define GMM_D 64
#define GMM_K 64
#define BS    128
#define TPB   128
#define NJP   32          // f32x2 pair steps for one 64-dim GEMM
#define RSXF  66          // sX row stride in floats (= 33 ulls, 264 B: 8B-aligned rows)
#define RSXU  33          // sX row stride in ulls
#define RSW   33          // sW row stride (ull pairs)
#define RSO   132         // epilogue sO row stride (floats)

typedef unsigned long long ull;

__device__ __forceinline__ ull fma2(ull a, ull b, ull c) {
    ull d; asm("fma.rn.f32x2 %0, %1, %2, %3;" : "=l"(d) : "l"(a), "l"(b), "l"(c)); return d;
}
__device__ __forceinline__ ull pack2(float lo, float hi) {
    ull r; asm("mov.b64 %0, {%1, %2};" : "=l"(r) : "f"(lo), "f"(hi)); return r;
}
__device__ __forceinline__ void unpack2(ull v, float& lo, float& hi) {
    asm("mov.b64 {%0, %1}, %2;" : "=f"(lo), "=f"(hi) : "l"(v));
}

// smem layout, ~102 KB total -> 2 CTAs/SM
//  sX  : float[128][66]   x tile   (overlaid by sO[64][132] after GEMM)
//  sX2 : float[128][66]   x^2 tile (general path only)
//  sWB : ull[64][33]      B  = mu*e^{-lv}, f32x2 pairs along d
//  sWA : ull[64][33]      A' = -0.5*e^{-lv}
//  sC  : float[64], sLse : float[128], sFlag : int

__global__ void __launch_bounds__(TPB, 2)
gmm_fused(const float* __restrict__ X, const float* __restrict__ mu,
          const float* __restrict__ lv, const float* __restrict__ lp,
          float* __restrict__ out, int N) {
    extern __shared__ char smraw[];
    float* sX   = (float*)smraw;                       // 128*66 floats
    float* sX2  = sX + 128 * RSXF;                     // 128*66 floats
    ull*   sWB  = (ull*)(sX2 + 128 * RSXF);            // 64*33 (byte offset 67584, 8B-aligned)
    ull*   sWA  = sWB + GMM_K * RSW;                   // 64*33
    float* sC   = (float*)(sWA + GMM_K * RSW);         // 64
    float* sLse = sC + GMM_K;                          // 128
    int*   sFlag= (int*)(sLse + BS);
    float* sO   = sX;                                  // overlay: 64 x 132 floats

    const int t  = threadIdx.x;
    const int n0 = blockIdx.x * BS;

    if (t == 0) *sFlag = 0;
    __syncthreads();

    // ---- stage W tiles + logvar k-uniformity check + C[k] ----
    {
        const float2* mu2 = (const float2*)mu;
        const float2* lv2 = (const float2*)lv;
        int bad = 0;
        #pragma unroll
        for (int i = 0; i < 16; i++) {
            int idx = i * TPB + t;            // 0..2047 pair slots
            int k   = idx >> 5;
            int jp  = idx & 31;
            float2 m = mu2[k * 32 + jp];
            float2 l = lv2[k * 32 + jp];
            float2 l0 = lv2[jp];              // row 0 (L2-hot)
            bad |= (__float_as_int(l.x) != __float_as_int(l0.x)) |
                   (__float_as_int(l.y) != __float_as_int(l0.y));
            float e0 = __expf(-l.x), e1 = __expf(-l.y);
            sWB[k * RSW + jp] = pack2(m.x * e0, m.y * e1);
            sWA[k * RSW + jp] = pack2(-0.5f * e0, -0.5f * e1);
        }
        if (bad) atomicOr(sFlag, 1);

        if (t < GMM_K) {
            float s = 0.f;
            #pragma unroll 8
            for (int d = 0; d < GMM_D; d++) {
                float l = lv[t * GMM_D + d];
                float m = mu[t * GMM_D + d];
                s += l + m * m * __expf(-l);
            }
            sC[t] = -0.5f * s + lp[t];
        }
    }
    __syncthreads();

    const int general = *sFlag;

    // ---- stage X (and x^2 if general): float4 global loads, float2 smem stores ----
    {
        const float4* xg4 = (const float4*)(X + (size_t)n0 * GMM_D);
        #pragma unroll
        for (int i = 0; i < 16; i++) {
            int idx = i * TPB + t;            // 0..2047 float4 slots
            int n   = idx >> 4;
            int d0  = (idx & 15) * 4;
            float4 v = xg4[idx];
            float* p = &sX[n * RSXF + d0];
            *(float2*)p       = make_float2(v.x, v.y);
            *(float2*)(p + 2) = make_float2(v.z, v.w);
            if (general) {
                float* q = &sX2[n * RSXF + d0];
                *(float2*)q       = make_float2(v.x * v.x, v.y * v.y);
                *(float2*)(q + 2) = make_float2(v.z * v.z, v.w * v.w);
            }
        }
    }
    __syncthreads();

    // ---- GEMM: thread tile 8 samples x 8 k ----
    const int ts = t & 15;                    // samples ts + 16m
    const int tk = t >> 4;                    // k = tk + 8q

    ull acc[8][8];
    #pragma unroll
    for (int m = 0; m < 8; m++)
        #pragma unroll
        for (int q = 0; q < 8; q++) acc[m][q] = 0ull;

    {
        const ull* xb = (const ull*)sX + ts * RSXU;
        const ull* wb = sWB + tk * RSW;
        #pragma unroll 2
        for (int jp = 0; jp < NJP; jp++) {
            ull wv[8], xv[8];
            #pragma unroll
            for (int q = 0; q < 8; q++) wv[q] = wb[q * 8 * RSW + jp];
            #pragma unroll
            for (int m = 0; m < 8; m++) xv[m] = xb[m * 16 * RSXU + jp];
            #pragma unroll
            for (int m = 0; m < 8; m++)
                #pragma unroll
                for (int q = 0; q < 8; q++)
                    acc[m][q] = fma2(xv[m], wv[q], acc[m][q]);
        }
    }
    if (general) {                            // x^2 * A' GEMM (skipped when lv k-uniform)
        const ull* xb = (const ull*)sX2 + ts * RSXU;
        const ull* wb = sWA + tk * RSW;
        #pragma unroll 2
        for (int jp = 0; jp < NJP; jp++) {
            ull wv[8], xv[8];
            #pragma unroll
            for (int q = 0; q < 8; q++) wv[q] = wb[q * 8 * RSW + jp];
            #pragma unroll
            for (int m = 0; m < 8; m++) xv[m] = xb[m * 16 * RSXU + jp];
            #pragma unroll
            for (int m = 0; m < 8; m++)
                #pragma unroll
                for (int q = 0; q < 8; q++)
                    acc[m][q] = fma2(xv[m], wv[q], acc[m][q]);
        }
    }

    // ---- finalize + scatter to sO[k][n] ----
    float w[8][8];
    #pragma unroll
    for (int q = 0; q < 8; q++) {
        float ck = sC[tk + 8 * q];
        #pragma unroll
        for (int m = 0; m < 8; m++) {
            float lo, hi; unpack2(acc[m][q], lo, hi);
            w[m][q] = lo + hi + ck;
        }
    }
    __syncthreads();                          // X tiles dead -> sO overlay
    #pragma unroll
    for (int q = 0; q < 8; q++) {
        const int k = tk + 8 * q;
        #pragma unroll
        for (int m = 0; m < 8; m++)
            sO[k * RSO + ts + 16 * m] = w[m][q];
    }
    __syncthreads();

    // ---- per-sample logsumexp over k ----
    {
        float mx = -INFINITY;
        #pragma unroll 8
        for (int k = 0; k < GMM_K; k++) mx = fmaxf(mx, sO[k * RSO + t]);
        float s = 0.f;
        #pragma unroll 8
        for (int k = 0; k < GMM_K; k++) s += __expf(sO[k * RSO + t] - mx);
        sLse[t] = mx + __logf(s);
    }
    __syncthreads();

    // ---- coalesced float4 writeout ----
    {
        const int kq   = t >> 5;
        const int lane = t & 31;
        float4 L = ((const float4*)sLse)[lane];
        #pragma unroll
        for (int i = 0; i < 16; i++) {
            int k = i * 4 + kq;
            float4 v = *(const float4*)&sO[k * RSO + lane * 4];
            float4 r;
            r.x = v.x - L.x; r.y = v.y - L.y; r.z = v.z - L.z; r.w = v.w - L.w;
            *(float4*)(out + (size_t)k * N + n0 + lane * 4) = r;
        }
    }
}

extern "C" void kernel_launch(void* const* d_in, const int* in_sizes, int n_in,
                              void* d_out, int out_size) {
    const float* X  = (const float*)d_in[0];
    const float* mu = (const float*)d_in[1];
    const float* lv = (const float*)d_in[2];
    const float* lp = (const float*)d_in[3];
    float* out = (float*)d_out;

    const int K = in_sizes[3];            // 64
    const int D = in_sizes[1] / K;        // 64
    const int N = in_sizes[0] / D;        // 131072

    const size_t smem = (size_t)(2 * 128 * RSXF) * sizeof(float)
                      + (size_t)(2 * GMM_K * RSW) * sizeof(ull)
                      + (GMM_K + BS) * sizeof(float) + 16;
    cudaFuncSetAttribute(gmm_fused, cudaFuncAttributeMaxDynamicSharedMemorySize, (int)smem);
    gmm_fused<<<N / BS, TPB, smem>>>(X, mu, lv, lp, out, N);
}